// round 16
// baseline (speedup 1.0000x reference)
#include <cuda_runtime.h>
#include <cuda_fp16.h>
#include <math.h>
#include <stdint.h>

#define INV_SCALE 0.08838834764831845f  // 1/sqrt(128)

// ------------------------- static scratch (no cudaMalloc) -------------------
__device__ float  g_bias[16 * 4096];
__device__ __half g_xh[4096UL * 1024];
__device__ __half g_peh[2048UL * 1024];
__device__ __half g_wth[3072UL * 1024];     // W_tok^T (hi only)
__device__ __half g_wph[2048UL * 1024];     // W_pos^T (hi only)
__device__ __half g_qh[32UL * 2048 * 128];
__device__ __half g_kh[32UL * 2048 * 128];
__device__ __half g_vh[32UL * 2048 * 64];   // V per z: [s][64] natural layout

// ---------------------------------------------------------------------------
__device__ __forceinline__ void mma16816(float c[4], const uint32_t a[4],
                                         const uint32_t b[2]) {
    asm volatile(
        "mma.sync.aligned.m16n8k16.row.col.f32.f16.f16.f32 "
        "{%0,%1,%2,%3}, {%4,%5,%6,%7}, {%8,%9}, {%0,%1,%2,%3};\n"
        : "+f"(c[0]), "+f"(c[1]), "+f"(c[2]), "+f"(c[3])
        : "r"(a[0]), "r"(a[1]), "r"(a[2]), "r"(a[3]), "r"(b[0]), "r"(b[1]));
}
__device__ __forceinline__ uint32_t sptr(const void* p) {
    return (uint32_t)__cvta_generic_to_shared(p);
}
__device__ __forceinline__ void ldsm4(uint32_t r[4], const __half* p) {
    asm volatile("ldmatrix.sync.aligned.m8n8.x4.shared.b16 {%0,%1,%2,%3}, [%4];\n"
                 : "=r"(r[0]), "=r"(r[1]), "=r"(r[2]), "=r"(r[3]) : "r"(sptr(p)));
}
__device__ __forceinline__ void ldsm4t(uint32_t r[4], const __half* p) {
    asm volatile("ldmatrix.sync.aligned.m8n8.x4.trans.shared.b16 {%0,%1,%2,%3}, [%4];\n"
                 : "=r"(r[0]), "=r"(r[1]), "=r"(r[2]), "=r"(r[3]) : "r"(sptr(p)));
}
__device__ __forceinline__ void cpa16(__half* dst, const __half* src) {
    asm volatile("cp.async.cg.shared.global [%0], [%1], 16;\n"
                 :: "r"(sptr(dst)), "l"(src));
}
#define CP_COMMIT() asm volatile("cp.async.commit_group;\n")
#define CP_WAIT1() asm volatile("cp.async.wait_group 1;\n")
#define CP_WAIT0() asm volatile("cp.async.wait_group 0;\n")

// ---------------------------------------------------------------------------
// fused: pack x -> xh, pos_embed -> peh (fp16 hi only), and T5 bias LUT
// ---------------------------------------------------------------------------
constexpr int N4X = 4096 * 1024 / 4;   // 1048576
constexpr int N4P = 2048 * 1024 / 4;   // 524288
constexpr int NB  = 16 * 4096;         // 65536
__global__ void pack_all_h(const float* __restrict__ x,
                           const float* __restrict__ pe,
                           const float* __restrict__ bias_table) {
    int i = blockIdx.x * blockDim.x + threadIdx.x;
    if (i < N4X + N4P) {
        const float* src;
        __half* dst;
        int j;
        if (i < N4X) { src = x;  dst = g_xh;  j = i; }
        else         { src = pe; dst = g_peh; j = i - N4X; }
        float4 v = ((const float4*)src)[j];
        ((__half2*)dst)[2 * j]     = __floats2half2_rn(v.x, v.y);
        ((__half2*)dst)[2 * j + 1] = __floats2half2_rn(v.z, v.w);
    } else if (i < N4X + N4P + NB) {
        int j = i - N4X - N4P;
        int h = j >> 12, dd = j & 4095;
        int n = -(dd - 2047);
        int ret = 0;
        if (n < 0) { ret = 16; n = -n; }
        int bucket;
        if (n < 8) bucket = n;
        else {
            float v = logf((float)n / 8.0f) / logf(16.0f) * 8.0f;
            int vi = 8 + (int)v;
            bucket = vi < 15 ? vi : 15;
        }
        g_bias[j] = bias_table[(bucket + ret + 2048) * 16 + h];
    }
}

// ---------------------------------------------------------------------------
// fused pack+transpose for both weights: src [1024][N] -> dst [N][1024], fp16
// ---------------------------------------------------------------------------
__global__ void __launch_bounds__(256) pack_splitT_all(
    const float* __restrict__ wt, const float* __restrict__ wp) {
    __shared__ float tile[32][33];
    const float* src;
    __half* hi;
    int N, bx = blockIdx.x;
    if (bx < 96) { src = wt; hi = g_wth; N = 3072; }
    else         { src = wp; hi = g_wph; N = 2048; bx -= 96; }
    int n0 = bx * 32, k0 = blockIdx.y * 32;
    int tx = threadIdx.x, ty = threadIdx.y;
#pragma unroll
    for (int t = 0; t < 4; t++)
        tile[ty + t * 8][tx] = src[(size_t)(k0 + ty + t * 8) * N + n0 + tx];
    __syncthreads();
#pragma unroll
    for (int t = 0; t < 4; t++) {
        int n = n0 + ty + t * 8;
        hi[(size_t)n * 1024 + k0 + tx] = __float2half_rn(tile[tx][ty + t * 8]);
    }
}

// ---------------------------------------------------------------------------
// merged 1-term GEMM with FUSED Q/K/V epilogue (no fp32 intermediate):
// blocks [0,768): tok proj: key->kh[:, :64], query->qh (scaled), value->vh
// blocks [768,1024): pos proj: -> kh/qh [:, 64:128], duplicated to both b
// 128x128 tile, 8 warps, k-step 32, 3-stage cp.async, 2 CTAs/SM.
// ---------------------------------------------------------------------------
constexpr int HSTR = 40;
constexpr int HG_STG = 128 * HSTR;
constexpr int HG_STAGE = 2 * HG_STG;            // A, Bh
constexpr int HG_SMEM = 3 * HG_STAGE * 2;       // 61440 bytes

__global__ void __launch_bounds__(256, 2) hgemm2(
    const __half* __restrict__ At, const __half* __restrict__ Bht,
    const __half* __restrict__ Ap, const __half* __restrict__ Bhp)
{
    extern __shared__ __half smg[];
    const int tid = threadIdx.x, wid = tid >> 5, lane = tid & 31;
    const int wm = wid & 1, wn = wid >> 1;
    const __half *A, *Bh;
    int bx, by, isTok;
    {
        int bid = blockIdx.x;
        if (bid < 768) { A = At; Bh = Bht; isTok = 1;
                         bx = bid % 24; by = bid / 24; }
        else { bid -= 768; A = Ap; Bh = Bhp; isTok = 0;
               bx = bid % 16; by = bid / 16; }
    }
    const int bm = by * 128, bn = bx * 128;
    const int lrow = tid >> 2, lgc = (tid & 3) * 8;
    const __half* pA0 = A + (size_t)(bm + lrow) * 1024 + lgc;
    const __half* pA1 = A + (size_t)(bm + lrow + 64) * 1024 + lgc;
    const __half* pBh0 = Bh + (size_t)(bn + lrow) * 1024 + lgc;
    const __half* pBh1 = Bh + (size_t)(bn + lrow + 64) * 1024 + lgc;
    const int so0 = lrow * HSTR + lgc, so1 = (lrow + 64) * HSTR + lgc;
    const int aoff = (lane & 15) * HSTR + (lane >> 4) * 8;
    const int boff = ((lane & 7) + ((lane >> 4) << 3)) * HSTR + ((lane >> 3) & 1) * 8;
    float acc[4][4][4] = {};

    auto LOAD = [&](int c) {
        __half* st = smg + (c % 3) * HG_STAGE;
        const int k0 = c * 32;
        cpa16(st + so0, pA0 + k0);
        cpa16(st + so1, pA1 + k0);
        cpa16(st + HG_STG + so0, pBh0 + k0);
        cpa16(st + HG_STG + so1, pBh1 + k0);
        CP_COMMIT();
    };

    LOAD(0);
    LOAD(1);
    CP_WAIT1();
    __syncthreads();

    for (int kt = 0; kt < 32; kt++) {
        const __half* st = smg + (kt % 3) * HG_STAGE;
#pragma unroll
        for (int kd = 0; kd < 2; kd++) {
            uint32_t af[4][4], bfh[4][2];
#pragma unroll
            for (int i = 0; i < 4; i++)
                ldsm4(af[i], st + (wm * 64 + i * 16) * HSTR + kd * 16 + aoff);
#pragma unroll
            for (int j2 = 0; j2 < 2; j2++) {
                uint32_t t4[4];
                ldsm4(t4, st + HG_STG + (wn * 32 + j2 * 16) * HSTR + kd * 16 + boff);
                bfh[2 * j2][0] = t4[0]; bfh[2 * j2][1] = t4[1];
                bfh[2 * j2 + 1][0] = t4[2]; bfh[2 * j2 + 1][1] = t4[3];
            }
#pragma unroll
            for (int i = 0; i < 4; i++)
#pragma unroll
                for (int j = 0; j < 4; j++)
                    mma16816(acc[i][j], af[i], bfh[j]);
        }
        if (kt + 2 < 32) {
            LOAD(kt + 2);
            CP_WAIT1();
        } else {
            CP_WAIT0();
        }
        __syncthreads();
    }

    // ---- fused epilogue: write Q/K/V directly in attention layout ----
    if (isTok) {
#pragma unroll
        for (int i = 0; i < 4; i++) {
            int r = bm + wm * 64 + i * 16 + (lane >> 2);
            int bb = r >> 11, s = r & 2047;
#pragma unroll
            for (int j = 0; j < 4; j++) {
                int c = bn + wn * 32 + j * 8 + (lane & 3) * 2;
                int region = c >> 10, col = c & 1023;
                int h = col >> 6, dh = col & 63;
                size_t zs = (size_t)(bb * 16 + h) * 2048;
                if (region == 0) {
                    *(__half2*)&g_kh[(zs + s) * 128 + dh] =
                        __floats2half2_rn(acc[i][j][0], acc[i][j][1]);
                    *(__half2*)&g_kh[(zs + s + 8) * 128 + dh] =
                        __floats2half2_rn(acc[i][j][2], acc[i][j][3]);
                } else if (region == 1) {
                    *(__half2*)&g_qh[(zs + s) * 128 + dh] = __floats2half2_rn(
                        acc[i][j][0] * INV_SCALE, acc[i][j][1] * INV_SCALE);
                    *(__half2*)&g_qh[(zs + s + 8) * 128 + dh] = __floats2half2_rn(
                        acc[i][j][2] * INV_SCALE, acc[i][j][3] * INV_SCALE);
                } else {
                    *(__half2*)&g_vh[(zs + s) * 64 + dh] =
                        __floats2half2_rn(acc[i][j][0], acc[i][j][1]);
                    *(__half2*)&g_vh[(zs + s + 8) * 64 + dh] =
                        __floats2half2_rn(acc[i][j][2], acc[i][j][3]);
                }
            }
        }
    } else {
#pragma unroll
        for (int i = 0; i < 4; i++) {
            int s = bm + wm * 64 + i * 16 + (lane >> 2);
#pragma unroll
            for (int j = 0; j < 4; j++) {
                int c = bn + wn * 32 + j * 8 + (lane & 3) * 2;
                int region = c >> 10, col = c & 1023;
                int h = col >> 6, dh = 64 + (col & 63);
                if (region == 0) {
                    __half2 v01 = __floats2half2_rn(acc[i][j][0], acc[i][j][1]);
                    __half2 v23 = __floats2half2_rn(acc[i][j][2], acc[i][j][3]);
#pragma unroll
                    for (int bb = 0; bb < 2; bb++) {
                        size_t zs = (size_t)(bb * 16 + h) * 2048;
                        *(__half2*)&g_kh[(zs + s) * 128 + dh]     = v01;
                        *(__half2*)&g_kh[(zs + s + 8) * 128 + dh] = v23;
                    }
                } else {
                    __half2 q01 = __floats2half2_rn(acc[i][j][0] * INV_SCALE,
                                                    acc[i][j][1] * INV_SCALE);
                    __half2 q23 = __floats2half2_rn(acc[i][j][2] * INV_SCALE,
                                                    acc[i][j][3] * INV_SCALE);
#pragma unroll
                    for (int bb = 0; bb < 2; bb++) {
                        size_t zs = (size_t)(bb * 16 + h) * 2048;
                        *(__half2*)&g_qh[(zs + s) * 128 + dh]     = q01;
                        *(__half2*)&g_qh[(zs + s + 8) * 128 + dh] = q23;
                    }
                }
            }
        }
    }
}

// ---------------------------------------------------------------------------
// fused flash attention, no online max (logits bounded; fp32 exp safe):
// bias pre-loaded into the QK accumulators (moves LDG+add off the exp chain);
// exp/pack interleaved per-kf with PV mma. K-tile 64, 3-stage cp.async,
// 2 CTAs/SM. L reduced once at end. block = (q-tile 128, z), 8 warps.
// ---------------------------------------------------------------------------
#define QSTR 136
#define VSTR 72
constexpr int O_QH = 0;
constexpr int O_K  = 128 * QSTR;
constexpr int KHL  = 64 * QSTR;
constexpr int O_V  = O_K + 3 * KHL;
constexpr int VHL  = 64 * VSTR;
constexpr int ATT_SMEM = (O_V + 3 * VHL) * 2;    // 114688 bytes

__global__ void __launch_bounds__(256, 2) attn_kernel(
    const __half* __restrict__ qh,
    const __half* __restrict__ kh, const __half* __restrict__ vh,
    const float* __restrict__ biasd, float* __restrict__ out)
{
    extern __shared__ __half smh[];
    const int z = blockIdx.y, b = z >> 4, h = z & 15;
    const int q0 = blockIdx.x * 128;
    const int tid = threadIdx.x, wid = tid >> 5, lane = tid & 31;
    const int lr4 = lane >> 2, lc2 = (lane & 3) * 2;
    const float* bd = biasd + h * 4096;
    const size_t zq = (size_t)z * 2048 * 128;
    const size_t zv = (size_t)z * 2048 * 64;
    const int mrow = wid * 16;
    const int aoffQ = (lane & 15) * QSTR + (lane >> 4) * 8;
    const int boffK = ((lane & 7) + ((lane >> 4) << 3)) * QSTR + ((lane >> 3) & 1) * 8;
    const int boffVt = ((lane & 7) + ((lane >> 3) & 1) * 8) * VSTR + (lane >> 4) * 8;

    auto PREFETCH = [&](int t) {
        __half* bK = smh + O_K + (t % 3) * KHL;
        __half* bV = smh + O_V + (t % 3) * VHL;
        const int k0 = t * 64;
#pragma unroll
        for (int tt = 0; tt < 4; tt++) {
            int i = tid + tt * 256, r = i >> 4, c = (i & 15) * 8;
            cpa16(bK + r * QSTR + c, kh + zq + (size_t)(k0 + r) * 128 + c);
        }
#pragma unroll
        for (int tt = 0; tt < 2; tt++) {
            int i = tid + tt * 256, r = i >> 3, c = (i & 7) * 8;
            cpa16(bV + r * VSTR + c, vh + zv + (size_t)(k0 + r) * 64 + c);
        }
        CP_COMMIT();
    };

    // group 0: Q + K/V tile0 ; group 1: tile1
#pragma unroll
    for (int t = 0; t < 4; t++) {
        int i = tid + t * 256, r = i >> 3, c = (i & 7) * 16;
        cpa16(smh + O_QH + r * QSTR + c, qh + zq + (size_t)(q0 + r) * 128 + c);
        cpa16(smh + O_QH + r * QSTR + c + 8, qh + zq + (size_t)(q0 + r) * 128 + c + 8);
    }
    {
        __half* bK = smh + O_K;
        __half* bV = smh + O_V;
#pragma unroll
        for (int tt = 0; tt < 4; tt++) {
            int i = tid + tt * 256, r = i >> 4, c = (i & 15) * 8;
            cpa16(bK + r * QSTR + c, kh + zq + (size_t)r * 128 + c);
        }
#pragma unroll
        for (int tt = 0; tt < 2; tt++) {
            int i = tid + tt * 256, r = i >> 3, c = (i & 7) * 8;
            cpa16(bV + r * VSTR + c, vh + zv + (size_t)r * 64 + c);
        }
        CP_COMMIT();
    }
    PREFETCH(1);
    CP_WAIT1();          // Q + tile0 arrived
    __syncthreads();

    uint32_t qfh[8][4];
#pragma unroll
    for (int kd = 0; kd < 8; kd++)
        ldsm4(qfh[kd], smh + O_QH + mrow * QSTR + kd * 16 + aoffQ);

    float L0 = 0.f, L1 = 0.f;   // per-thread partial sums (reduced at end)
    float of[8][4] = {};
    const int r0 = q0 + mrow + lr4;

    for (int it = 0; it < 32; it++) {
        const int k0 = it * 64, stg = it % 3;
        const __half* bK = smh + O_K + stg * KHL;
        const __half* bV = smh + O_V + stg * VHL;

        // init S accumulators with the relative-position bias (hoists the
        // LDGs + adds out of the post-mma exp chain)
        float sf[8][4];
#pragma unroll
        for (int nf = 0; nf < 8; nf++) {
            int c = k0 + nf * 8 + lc2;
            sf[nf][0] = bd[c - r0 + 2047];
            sf[nf][1] = bd[c + 1 - r0 + 2047];
            sf[nf][2] = bd[c - (r0 + 8) + 2047];
            sf[nf][3] = bd[c + 1 - (r0 + 8) + 2047];
        }

        // S = bias + Q K^T
#pragma unroll
        for (int kd = 0; kd < 8; kd++) {
#pragma unroll
            for (int np = 0; np < 4; np++) {
                uint32_t b4[4];
                ldsm4(b4, bK + (np * 16) * QSTR + kd * 16 + boffK);
                mma16816(sf[2 * np],     qfh[kd], b4);
                mma16816(sf[2 * np + 1], qfh[kd], b4 + 2);
            }
        }

        // per-kf: exp + pack + PV mma (interleaves MUFU with tensor)
#pragma unroll
        for (int kf = 0; kf < 4; kf++) {
            uint32_t ap[4];
#pragma unroll
            for (int j = 0; j < 2; j++) {
                int nf = 2 * kf + j;
                float p0 = __expf(sf[nf][0]);
                float p1 = __expf(sf[nf][1]);
                float p2 = __expf(sf[nf][2]);
                float p3 = __expf(sf[nf][3]);
                L0 += p0 + p1;
                L1 += p2 + p3;
                __half2 h01 = __floats2half2_rn(p0, p1);
                __half2 h23 = __floats2half2_rn(p2, p3);
                ap[j * 2]     = *(uint32_t*)&h01;
                ap[j * 2 + 1] = *(uint32_t*)&h23;
            }
#pragma unroll
            for (int np = 0; np < 4; np++) {
                uint32_t b4[4];
                ldsm4t(b4, bV + (kf * 16) * VSTR + np * 16 + boffVt);
                mma16816(of[2 * np],     ap, b4);
                mma16816(of[2 * np + 1], ap, b4 + 2);
            }
        }

        if (it + 2 < 32) {
            PREFETCH(it + 2);
            CP_WAIT1();
        } else {
            CP_WAIT0();
        }
        __syncthreads();
    }

    // final row-sum reduction (once, not per tile)
    L0 += __shfl_xor_sync(0xffffffffu, L0, 1);
    L0 += __shfl_xor_sync(0xffffffffu, L0, 2);
    L1 += __shfl_xor_sync(0xffffffffu, L1, 1);
    L1 += __shfl_xor_sync(0xffffffffu, L1, 2);
    float inv0 = 1.f / L0, inv1 = 1.f / L1;
    const size_t ob = (size_t)b * 2048 * 1024 + h * 64;
#pragma unroll
    for (int nf = 0; nf < 8; nf++) {
        int c = nf * 8 + lc2;
        *(float2*)&out[ob + (size_t)r0 * 1024 + c] =
            make_float2(of[nf][0] * inv0, of[nf][1] * inv0);
        *(float2*)&out[ob + (size_t)(r0 + 8) * 1024 + c] =
            make_float2(of[nf][2] * inv1, of[nf][3] * inv1);
    }
}

// ---------------------------------------------------------------------------
extern "C" void kernel_launch(void* const* d_in, const int* in_sizes, int n_in,
                              void* d_out, int out_size)
{
    const float* x          = (const float*)d_in[0];
    const float* pos_embed  = (const float*)d_in[1];
    const float* W_pos_kq   = (const float*)d_in[2];
    const float* W_tok_kqv  = (const float*)d_in[3];
    const float* bias_table = (const float*)d_in[4];
    float* out = (float*)d_out;

    float* biasd;
    __half *xh, *peh, *wth, *wph;
    __half *qh, *kh, *vh;
    cudaGetSymbolAddress((void**)&biasd, g_bias);
    cudaGetSymbolAddress((void**)&xh, g_xh);
    cudaGetSymbolAddress((void**)&peh, g_peh);
    cudaGetSymbolAddress((void**)&wth, g_wth);
    cudaGetSymbolAddress((void**)&wph, g_wph);
    cudaGetSymbolAddress((void**)&qh, g_qh);
    cudaGetSymbolAddress((void**)&kh, g_kh);
    cudaGetSymbolAddress((void**)&vh, g_vh);

    cudaFuncSetAttribute(attn_kernel,
                         cudaFuncAttributeMaxDynamicSharedMemorySize, ATT_SMEM);
    cudaFuncSetAttribute(hgemm2,
                         cudaFuncAttributeMaxDynamicSharedMemorySize, HG_SMEM);

    pack_all_h<<<(N4X + N4P + NB + 255) / 256, 256>>>(x, pos_embed, bias_table);
    pack_splitT_all<<<dim3(160, 32), dim3(32, 8)>>>(W_tok_kqv, W_pos_kq);
    hgemm2<<<1024, 256, HG_SMEM>>>(xh, wth, peh, wph);
    attn_kernel<<<dim3(16, 32), 256, ATT_SMEM>>>(qh, kh, vh, biasd, out);
}

// round 17
// speedup vs baseline: 1.0612x; 1.0612x over previous
#include <cuda_runtime.h>
#include <cuda_fp16.h>
#include <math.h>
#include <stdint.h>

#define INV_SCALE 0.08838834764831845f   // 1/sqrt(128)
#define LOG2E 1.4426950408889634f
#define QSCALE (INV_SCALE * LOG2E)       // folded: logits in base-2 domain

// ------------------------- static scratch (no cudaMalloc) -------------------
__device__ float  g_bias[16 * 4096];     // bias * log2e
__device__ __half g_xh[4096UL * 1024];
__device__ __half g_peh[2048UL * 1024];
__device__ __half g_wth[3072UL * 1024];  // W_tok^T (hi only)
__device__ __half g_wph[2048UL * 1024];  // W_pos^T (hi only)
__device__ __half g_qh[32UL * 2048 * 128];
__device__ __half g_kh[32UL * 2048 * 128];
__device__ __half g_vh[32UL * 2048 * 64];

// ---------------------------------------------------------------------------
__device__ __forceinline__ void mma16816(float c[4], const uint32_t a[4],
                                         const uint32_t b[2]) {
    asm volatile(
        "mma.sync.aligned.m16n8k16.row.col.f32.f16.f16.f32 "
        "{%0,%1,%2,%3}, {%4,%5,%6,%7}, {%8,%9}, {%0,%1,%2,%3};\n"
        : "+f"(c[0]), "+f"(c[1]), "+f"(c[2]), "+f"(c[3])
        : "r"(a[0]), "r"(a[1]), "r"(a[2]), "r"(a[3]), "r"(b[0]), "r"(b[1]));
}
__device__ __forceinline__ uint32_t sptr(const void* p) {
    return (uint32_t)__cvta_generic_to_shared(p);
}
__device__ __forceinline__ void ldsm4(uint32_t r[4], const __half* p) {
    asm volatile("ldmatrix.sync.aligned.m8n8.x4.shared.b16 {%0,%1,%2,%3}, [%4];\n"
                 : "=r"(r[0]), "=r"(r[1]), "=r"(r[2]), "=r"(r[3]) : "r"(sptr(p)));
}
__device__ __forceinline__ void ldsm4t(uint32_t r[4], const __half* p) {
    asm volatile("ldmatrix.sync.aligned.m8n8.x4.trans.shared.b16 {%0,%1,%2,%3}, [%4];\n"
                 : "=r"(r[0]), "=r"(r[1]), "=r"(r[2]), "=r"(r[3]) : "r"(sptr(p)));
}
__device__ __forceinline__ void cpa16(__half* dst, const __half* src) {
    asm volatile("cp.async.cg.shared.global [%0], [%1], 16;\n"
                 :: "r"(sptr(dst)), "l"(src));
}
__device__ __forceinline__ uint32_t ex2_f16x2(uint32_t x) {
    uint32_t r;
    asm("ex2.approx.f16x2 %0, %1;\n" : "=r"(r) : "r"(x));
    return r;
}
#define CP_COMMIT() asm volatile("cp.async.commit_group;\n")
#define CP_WAIT1() asm volatile("cp.async.wait_group 1;\n")
#define CP_WAIT0() asm volatile("cp.async.wait_group 0;\n")

// ---------------------------------------------------------------------------
// fused: pack x -> xh, pos_embed -> peh (fp16 hi only), and T5 bias LUT
// (bias pre-multiplied by log2e for base-2 exp)
// ---------------------------------------------------------------------------
constexpr int N4X = 4096 * 1024 / 4;   // 1048576
constexpr int N4P = 2048 * 1024 / 4;   // 524288
constexpr int NB  = 16 * 4096;         // 65536
__global__ void pack_all_h(const float* __restrict__ x,
                           const float* __restrict__ pe,
                           const float* __restrict__ bias_table) {
    int i = blockIdx.x * blockDim.x + threadIdx.x;
    if (i < N4X + N4P) {
        const float* src;
        __half* dst;
        int j;
        if (i < N4X) { src = x;  dst = g_xh;  j = i; }
        else         { src = pe; dst = g_peh; j = i - N4X; }
        float4 v = ((const float4*)src)[j];
        ((__half2*)dst)[2 * j]     = __floats2half2_rn(v.x, v.y);
        ((__half2*)dst)[2 * j + 1] = __floats2half2_rn(v.z, v.w);
    } else if (i < N4X + N4P + NB) {
        int j = i - N4X - N4P;
        int h = j >> 12, dd = j & 4095;
        int n = -(dd - 2047);
        int ret = 0;
        if (n < 0) { ret = 16; n = -n; }
        int bucket;
        if (n < 8) bucket = n;
        else {
            float v = logf((float)n / 8.0f) / logf(16.0f) * 8.0f;
            int vi = 8 + (int)v;
            bucket = vi < 15 ? vi : 15;
        }
        g_bias[j] = bias_table[(bucket + ret + 2048) * 16 + h] * LOG2E;
    }
}

// ---------------------------------------------------------------------------
// fused pack+transpose for both weights: src [1024][N] -> dst [N][1024], fp16
// ---------------------------------------------------------------------------
__global__ void __launch_bounds__(256) pack_splitT_all(
    const float* __restrict__ wt, const float* __restrict__ wp) {
    __shared__ float tile[32][33];
    const float* src;
    __half* hi;
    int N, bx = blockIdx.x;
    if (bx < 96) { src = wt; hi = g_wth; N = 3072; }
    else         { src = wp; hi = g_wph; N = 2048; bx -= 96; }
    int n0 = bx * 32, k0 = blockIdx.y * 32;
    int tx = threadIdx.x, ty = threadIdx.y;
#pragma unroll
    for (int t = 0; t < 4; t++)
        tile[ty + t * 8][tx] = src[(size_t)(k0 + ty + t * 8) * N + n0 + tx];
    __syncthreads();
#pragma unroll
    for (int t = 0; t < 4; t++) {
        int n = n0 + ty + t * 8;
        hi[(size_t)n * 1024 + k0 + tx] = __float2half_rn(tile[tx][ty + t * 8]);
    }
}

// ---------------------------------------------------------------------------
// merged 1-term GEMM with FUSED Q/K/V epilogue (Q pre-scaled by 1/sqrt(128)*log2e)
// ---------------------------------------------------------------------------
constexpr int HSTR = 40;
constexpr int HG_STG = 128 * HSTR;
constexpr int HG_STAGE = 2 * HG_STG;            // A, Bh
constexpr int HG_SMEM = 3 * HG_STAGE * 2;       // 61440 bytes

__global__ void __launch_bounds__(256, 2) hgemm2(
    const __half* __restrict__ At, const __half* __restrict__ Bht,
    const __half* __restrict__ Ap, const __half* __restrict__ Bhp)
{
    extern __shared__ __half smg[];
    const int tid = threadIdx.x, wid = tid >> 5, lane = tid & 31;
    const int wm = wid & 1, wn = wid >> 1;
    const __half *A, *Bh;
    int bx, by, isTok;
    {
        int bid = blockIdx.x;
        if (bid < 768) { A = At; Bh = Bht; isTok = 1;
                         bx = bid % 24; by = bid / 24; }
        else { bid -= 768; A = Ap; Bh = Bhp; isTok = 0;
               bx = bid % 16; by = bid / 16; }
    }
    const int bm = by * 128, bn = bx * 128;
    const int lrow = tid >> 2, lgc = (tid & 3) * 8;
    const __half* pA0 = A + (size_t)(bm + lrow) * 1024 + lgc;
    const __half* pA1 = A + (size_t)(bm + lrow + 64) * 1024 + lgc;
    const __half* pBh0 = Bh + (size_t)(bn + lrow) * 1024 + lgc;
    const __half* pBh1 = Bh + (size_t)(bn + lrow + 64) * 1024 + lgc;
    const int so0 = lrow * HSTR + lgc, so1 = (lrow + 64) * HSTR + lgc;
    const int aoff = (lane & 15) * HSTR + (lane >> 4) * 8;
    const int boff = ((lane & 7) + ((lane >> 4) << 3)) * HSTR + ((lane >> 3) & 1) * 8;
    float acc[4][4][4] = {};

    auto LOAD = [&](int c) {
        __half* st = smg + (c % 3) * HG_STAGE;
        const int k0 = c * 32;
        cpa16(st + so0, pA0 + k0);
        cpa16(st + so1, pA1 + k0);
        cpa16(st + HG_STG + so0, pBh0 + k0);
        cpa16(st + HG_STG + so1, pBh1 + k0);
        CP_COMMIT();
    };

    LOAD(0);
    LOAD(1);
    CP_WAIT1();
    __syncthreads();

    for (int kt = 0; kt < 32; kt++) {
        const __half* st = smg + (kt % 3) * HG_STAGE;
#pragma unroll
        for (int kd = 0; kd < 2; kd++) {
            uint32_t af[4][4], bfh[4][2];
#pragma unroll
            for (int i = 0; i < 4; i++)
                ldsm4(af[i], st + (wm * 64 + i * 16) * HSTR + kd * 16 + aoff);
#pragma unroll
            for (int j2 = 0; j2 < 2; j2++) {
                uint32_t t4[4];
                ldsm4(t4, st + HG_STG + (wn * 32 + j2 * 16) * HSTR + kd * 16 + boff);
                bfh[2 * j2][0] = t4[0]; bfh[2 * j2][1] = t4[1];
                bfh[2 * j2 + 1][0] = t4[2]; bfh[2 * j2 + 1][1] = t4[3];
            }
#pragma unroll
            for (int i = 0; i < 4; i++)
#pragma unroll
                for (int j = 0; j < 4; j++)
                    mma16816(acc[i][j], af[i], bfh[j]);
        }
        if (kt + 2 < 32) {
            LOAD(kt + 2);
            CP_WAIT1();
        } else {
            CP_WAIT0();
        }
        __syncthreads();
    }

    // ---- fused epilogue: write Q/K/V directly in attention layout ----
    if (isTok) {
#pragma unroll
        for (int i = 0; i < 4; i++) {
            int r = bm + wm * 64 + i * 16 + (lane >> 2);
            int bb = r >> 11, s = r & 2047;
#pragma unroll
            for (int j = 0; j < 4; j++) {
                int c = bn + wn * 32 + j * 8 + (lane & 3) * 2;
                int region = c >> 10, col = c & 1023;
                int h = col >> 6, dh = col & 63;
                size_t zs = (size_t)(bb * 16 + h) * 2048;
                if (region == 0) {
                    *(__half2*)&g_kh[(zs + s) * 128 + dh] =
                        __floats2half2_rn(acc[i][j][0], acc[i][j][1]);
                    *(__half2*)&g_kh[(zs + s + 8) * 128 + dh] =
                        __floats2half2_rn(acc[i][j][2], acc[i][j][3]);
                } else if (region == 1) {
                    *(__half2*)&g_qh[(zs + s) * 128 + dh] = __floats2half2_rn(
                        acc[i][j][0] * QSCALE, acc[i][j][1] * QSCALE);
                    *(__half2*)&g_qh[(zs + s + 8) * 128 + dh] = __floats2half2_rn(
                        acc[i][j][2] * QSCALE, acc[i][j][3] * QSCALE);
                } else {
                    *(__half2*)&g_vh[(zs + s) * 64 + dh] =
                        __floats2half2_rn(acc[i][j][0], acc[i][j][1]);
                    *(__half2*)&g_vh[(zs + s + 8) * 64 + dh] =
                        __floats2half2_rn(acc[i][j][2], acc[i][j][3]);
                }
            }
        }
    } else {
#pragma unroll
        for (int i = 0; i < 4; i++) {
            int s = bm + wm * 64 + i * 16 + (lane >> 2);
#pragma unroll
            for (int j = 0; j < 4; j++) {
                int c = bn + wn * 32 + j * 8 + (lane & 3) * 2;
                int region = c >> 10, col = c & 1023;
                int h = col >> 6, dh = 64 + (col & 63);
                if (region == 0) {
                    __half2 v01 = __floats2half2_rn(acc[i][j][0], acc[i][j][1]);
                    __half2 v23 = __floats2half2_rn(acc[i][j][2], acc[i][j][3]);
#pragma unroll
                    for (int bb = 0; bb < 2; bb++) {
                        size_t zs = (size_t)(bb * 16 + h) * 2048;
                        *(__half2*)&g_kh[(zs + s) * 128 + dh]     = v01;
                        *(__half2*)&g_kh[(zs + s + 8) * 128 + dh] = v23;
                    }
                } else {
                    __half2 q01 = __floats2half2_rn(acc[i][j][0] * QSCALE,
                                                    acc[i][j][1] * QSCALE);
                    __half2 q23 = __floats2half2_rn(acc[i][j][2] * QSCALE,
                                                    acc[i][j][3] * QSCALE);
#pragma unroll
                    for (int bb = 0; bb < 2; bb++) {
                        size_t zs = (size_t)(bb * 16 + h) * 2048;
                        *(__half2*)&g_qh[(zs + s) * 128 + dh]     = q01;
                        *(__half2*)&g_qh[(zs + s + 8) * 128 + dh] = q23;
                    }
                }
            }
        }
    }
}

// ---------------------------------------------------------------------------
// fused flash attention, no online max, base-2 logits:
// exp via ex2.approx.f16x2 (2 exps/MUFU op, output already packed fp16),
// L via ones-mma (fp32 row sums, no shuffle reduction).
// K-tile 64, 3-stage cp.async, 2 CTAs/SM. block = (q-tile 128, z), 8 warps.
// ---------------------------------------------------------------------------
#define QSTR 136
#define VSTR 72
constexpr int O_QH = 0;
constexpr int O_K  = 128 * QSTR;
constexpr int KHL  = 64 * QSTR;
constexpr int O_V  = O_K + 3 * KHL;
constexpr int VHL  = 64 * VSTR;
constexpr int ATT_SMEM = (O_V + 3 * VHL) * 2;    // 114688 bytes

__global__ void __launch_bounds__(256, 2) attn_kernel(
    const __half* __restrict__ qh,
    const __half* __restrict__ kh, const __half* __restrict__ vh,
    const float* __restrict__ biasd, float* __restrict__ out)
{
    extern __shared__ __half smh[];
    const int z = blockIdx.y, b = z >> 4, h = z & 15;
    const int q0 = blockIdx.x * 128;
    const int tid = threadIdx.x, wid = tid >> 5, lane = tid & 31;
    const int lr4 = lane >> 2, lc2 = (lane & 3) * 2;
    const float* bd = biasd + h * 4096;
    const size_t zq = (size_t)z * 2048 * 128;
    const size_t zv = (size_t)z * 2048 * 64;
    const int mrow = wid * 16;
    const int aoffQ = (lane & 15) * QSTR + (lane >> 4) * 8;
    const int boffK = ((lane & 7) + ((lane >> 4) << 3)) * QSTR + ((lane >> 3) & 1) * 8;
    const int boffVt = ((lane & 7) + ((lane >> 3) & 1) * 8) * VSTR + (lane >> 4) * 8;

    auto PREFETCH = [&](int t) {
        __half* bK = smh + O_K + (t % 3) * KHL;
        __half* bV = smh + O_V + (t % 3) * VHL;
        const int k0 = t * 64;
#pragma unroll
        for (int tt = 0; tt < 4; tt++) {
            int i = tid + tt * 256, r = i >> 4, c = (i & 15) * 8;
            cpa16(bK + r * QSTR + c, kh + zq + (size_t)(k0 + r) * 128 + c);
        }
#pragma unroll
        for (int tt = 0; tt < 2; tt++) {
            int i = tid + tt * 256, r = i >> 3, c = (i & 7) * 8;
            cpa16(bV + r * VSTR + c, vh + zv + (size_t)(k0 + r) * 64 + c);
        }
        CP_COMMIT();
    };

    // group 0: Q + K/V tile0 ; group 1: tile1
#pragma unroll
    for (int t = 0; t < 4; t++) {
        int i = tid + t * 256, r = i >> 3, c = (i & 7) * 16;
        cpa16(smh + O_QH + r * QSTR + c, qh + zq + (size_t)(q0 + r) * 128 + c);
        cpa16(smh + O_QH + r * QSTR + c + 8, qh + zq + (size_t)(q0 + r) * 128 + c + 8);
    }
    {
        __half* bK = smh + O_K;
        __half* bV = smh + O_V;
#pragma unroll
        for (int tt = 0; tt < 4; tt++) {
            int i = tid + tt * 256, r = i >> 4, c = (i & 15) * 8;
            cpa16(bK + r * QSTR + c, kh + zq + (size_t)r * 128 + c);
        }
#pragma unroll
        for (int tt = 0; tt < 2; tt++) {
            int i = tid + tt * 256, r = i >> 3, c = (i & 7) * 8;
            cpa16(bV + r * VSTR + c, vh + zv + (size_t)r * 64 + c);
        }
        CP_COMMIT();
    }
    PREFETCH(1);
    CP_WAIT1();          // Q + tile0 arrived
    __syncthreads();

    uint32_t qfh[8][4];
#pragma unroll
    for (int kd = 0; kd < 8; kd++)
        ldsm4(qfh[kd], smh + O_QH + mrow * QSTR + kd * 16 + aoffQ);

    const uint32_t ONES2 = 0x3C003C00u;   // (1.0h, 1.0h)
    const uint32_t ones_b[2] = {ONES2, ONES2};
    float oL[4] = {};                      // fp32 row-sum accumulators (ones-mma)
    float of[8][4] = {};
    const int r0 = q0 + mrow + lr4;

    for (int it = 0; it < 32; it++) {
        const int k0 = it * 64, stg = it % 3;
        const __half* bK = smh + O_K + stg * KHL;
        const __half* bV = smh + O_V + stg * VHL;

        // init S accumulators with bias (already * log2e)
        float sf[8][4];
#pragma unroll
        for (int nf = 0; nf < 8; nf++) {
            int c = k0 + nf * 8 + lc2;
            sf[nf][0] = bd[c - r0 + 2047];
            sf[nf][1] = bd[c + 1 - r0 + 2047];
            sf[nf][2] = bd[c - (r0 + 8) + 2047];
            sf[nf][3] = bd[c + 1 - (r0 + 8) + 2047];
        }

        // S = bias + Q K^T  (base-2 logits)
#pragma unroll
        for (int kd = 0; kd < 8; kd++) {
#pragma unroll
            for (int np = 0; np < 4; np++) {
                uint32_t b4[4];
                ldsm4(b4, bK + (np * 16) * QSTR + kd * 16 + boffK);
                mma16816(sf[2 * np],     qfh[kd], b4);
                mma16816(sf[2 * np + 1], qfh[kd], b4 + 2);
            }
        }

        // per-kf: f16x2 exp2 (packed) + ones-mma (L) + PV mma
#pragma unroll
        for (int kf = 0; kf < 4; kf++) {
            uint32_t ap[4];
#pragma unroll
            for (int j = 0; j < 2; j++) {
                int nf = 2 * kf + j;
                __half2 x01 = __floats2half2_rn(sf[nf][0], sf[nf][1]);
                __half2 x23 = __floats2half2_rn(sf[nf][2], sf[nf][3]);
                ap[j * 2]     = ex2_f16x2(*(uint32_t*)&x01);
                ap[j * 2 + 1] = ex2_f16x2(*(uint32_t*)&x23);
            }
            mma16816(oL, ap, ones_b);   // row sums of P (exact fp32)
#pragma unroll
            for (int np = 0; np < 4; np++) {
                uint32_t b4[4];
                ldsm4t(b4, bV + (kf * 16) * VSTR + np * 16 + boffVt);
                mma16816(of[2 * np],     ap, b4);
                mma16816(of[2 * np + 1], ap, b4 + 2);
            }
        }

        if (it + 2 < 32) {
            PREFETCH(it + 2);
            CP_WAIT1();
        } else {
            CP_WAIT0();
        }
        __syncthreads();
    }

    // oL[0] = full row sum for row r0, oL[2] for row r0+8 (no shuffles needed)
    float inv0 = 1.f / oL[0], inv1 = 1.f / oL[2];
    const size_t ob = (size_t)b * 2048 * 1024 + h * 64;
#pragma unroll
    for (int nf = 0; nf < 8; nf++) {
        int c = nf * 8 + lc2;
        *(float2*)&out[ob + (size_t)r0 * 1024 + c] =
            make_float2(of[nf][0] * inv0, of[nf][1] * inv0);
        *(float2*)&out[ob + (size_t)(r0 + 8) * 1024 + c] =
            make_float2(of[nf][2] * inv1, of[nf][3] * inv1);
    }
}

// ---------------------------------------------------------------------------
extern "C" void kernel_launch(void* const* d_in, const int* in_sizes, int n_in,
                              void* d_out, int out_size)
{
    const float* x          = (const float*)d_in[0];
    const float* pos_embed  = (const float*)d_in[1];
    const float* W_pos_kq   = (const float*)d_in[2];
    const float* W_tok_kqv  = (const float*)d_in[3];
    const float* bias_table = (const float*)d_in[4];
    float* out = (float*)d_out;

    float* biasd;
    __half *xh, *peh, *wth, *wph;
    __half *qh, *kh, *vh;
    cudaGetSymbolAddress((void**)&biasd, g_bias);
    cudaGetSymbolAddress((void**)&xh, g_xh);
    cudaGetSymbolAddress((void**)&peh, g_peh);
    cudaGetSymbolAddress((void**)&wth, g_wth);
    cudaGetSymbolAddress((void**)&wph, g_wph);
    cudaGetSymbolAddress((void**)&qh, g_qh);
    cudaGetSymbolAddress((void**)&kh, g_kh);
    cudaGetSymbolAddress((void**)&vh, g_vh);

    cudaFuncSetAttribute(attn_kernel,
                         cudaFuncAttributeMaxDynamicSharedMemorySize, ATT_SMEM);
    cudaFuncSetAttribute(hgemm2,
                         cudaFuncAttributeMaxDynamicSharedMemorySize, HG_SMEM);

    pack_all_h<<<(N4X + N4P + NB + 255) / 256, 256>>>(x, pos_embed, bias_table);
    pack_splitT_all<<<dim3(160, 32), dim3(32, 8)>>>(W_tok_kqv, W_pos_kq);
    hgemm2<<<1024, 256, HG_SMEM>>>(xh, wth, peh, wph);
    attn_kernel<<<dim3(16, 32), 256, ATT_SMEM>>>(qh, kh, vh, biasd, out);
}